// round 4
// baseline (speedup 1.0000x reference)
#include <cuda_runtime.h>

#define N_NODES 50000
#define T_STEPS 8
#define E_EDGES 800000
#define XD 128
#define HD 64
#define ZD 32
#define CAP 96   // max in-degree capacity; Poisson(16) tail beyond 96 ~ e^-80

// ---- scratch (no allocations allowed) ----
__device__ float g_xW1[N_NODES * HD];                       // x @ W1 (12.8 MB)
__device__ float g_hW2[(size_t)T_STEPS * N_NODES * ZD];     // per-t  (51.2 MB)
__device__ float g_dinv[T_STEPS * N_NODES];                 // rsqrt(deg)
__device__ int   g_count[T_STEPS * N_NODES];                // in-degree counters
__device__ int2  g_bins[(size_t)T_STEPS * N_NODES * CAP];   // (src, bits(w|nrm)) (307 MB)

// ============================================================
// Setup: g_xW1 = x @ W1   (warp per node, W1 in shared)
// ============================================================
__global__ void k_xw1(const float* __restrict__ x, const float* __restrict__ W1) {
    __shared__ float sW[XD * HD];  // 32 KB
    for (int i = threadIdx.x; i < XD * HD; i += blockDim.x) sW[i] = W1[i];
    __syncthreads();

    int node = blockIdx.x * (blockDim.x >> 5) + (threadIdx.x >> 5);
    int lane = threadIdx.x & 31;
    if (node >= N_NODES) return;

    const float* xr = x + node * XD;
    float xv[4];
    xv[0] = xr[lane];
    xv[1] = xr[lane + 32];
    xv[2] = xr[lane + 64];
    xv[3] = xr[lane + 96];

    float a0 = 0.f, a1 = 0.f;
#pragma unroll
    for (int q = 0; q < 4; q++) {
#pragma unroll
        for (int k = 0; k < 32; k++) {
            float xk = __shfl_sync(0xffffffffu, xv[q], k);
            int kk = q * 32 + k;
            a0 = fmaf(xk, sW[kk * HD + lane], a0);
            a1 = fmaf(xk, sW[kk * HD + lane + 32], a1);
        }
    }
    g_xW1[node * HD + lane]      = a0;
    g_xW1[node * HD + lane + 32] = a1;
}

// ============================================================
// Batched binning for ALL T steps
// ============================================================
__global__ void k_init() {
    int i = blockIdx.x * blockDim.x + threadIdx.x;
    if (i < T_STEPS * N_NODES) g_count[i] = 0;
}

__global__ void k_bin(const int* __restrict__ ei, const float* __restrict__ ew) {
    int idx = blockIdx.x * blockDim.x + threadIdx.x;
    if (idx >= T_STEPS * E_EDGES) return;
    int t = idx / E_EDGES;
    int e = idx - t * E_EDGES;
    const int* src = ei + (size_t)t * 2 * E_EDGES;
    const int* dst = src + E_EDGES;
    int s = src[e];
    int d = dst[e];
    float w = ew[(size_t)t * E_EDGES + e];
    int base = t * N_NODES + d;
    int p = atomicAdd(&g_count[base], 1);
    if (p < CAP) g_bins[(size_t)base * CAP + p] = make_int2(s, __float_as_int(w));
}

// deg = 1 + sum(w over bin entries); warp per node, warp-reduce
__global__ void k_dinv() {
    int node = blockIdx.x * (blockDim.x >> 5) + (threadIdx.x >> 5);  // 0..T*N-1
    int lane = threadIdx.x & 31;
    if (node >= T_STEPS * N_NODES) return;

    int c = min(g_count[node], CAP);
    const int2* bp = g_bins + (size_t)node * CAP;
    float s = 0.f;
    for (int j = lane; j < c; j += 32)
        s += __int_as_float(bp[j].y);
#pragma unroll
    for (int o = 16; o > 0; o >>= 1)
        s += __shfl_xor_sync(0xffffffffu, s, o);
    if (lane == 0) g_dinv[node] = rsqrtf(1.0f + s);
}

// ============================================================
// Fused layer 1 (ALL t): gather(xW1) + b1 + relu + (h @ W2) -> g_hW2[t]
// Warp per (t, node); lane owns dims {2*lane, 2*lane+1}; W2 column in regs.
// Prefetch converts bin w -> nrm (reused by layer 2).
// ============================================================
__global__ void __launch_bounds__(256) k_layer1(const float* __restrict__ b1,
                                                const float* __restrict__ W2) {
    __shared__ float sW[HD * ZD];  // 8 KB, row-major [64][32]
    for (int i = threadIdx.x; i < HD * ZD; i += blockDim.x) sW[i] = W2[i];
    __syncthreads();

    int t    = blockIdx.y;
    int node = blockIdx.x * (blockDim.x >> 5) + (threadIdx.x >> 5);
    int lane = threadIdx.x & 31;
    if (node >= N_NODES) return;

    // lane's output column of W2 in registers
    float wreg[HD];
#pragma unroll
    for (int k = 0; k < HD; k++) wreg[k] = sW[k * ZD + lane];

    int base = t * N_NODES + node;
    float dv = g_dinv[base];
    int   c  = min(g_count[base], CAP);
    const float* dinv_t = g_dinv + t * N_NODES;
    int2* bp = g_bins + (size_t)base * CAP;

    // coalesced prefetch: lane handles entries lane, lane+32, lane+64
    int   sj[3];
    float nj[3];
#pragma unroll
    for (int r = 0; r < 3; r++) {
        int j = lane + 32 * r;
        sj[r] = 0; nj[r] = 0.f;
        if (j < c) {
            int2 ent = bp[j];
            int s = ent.x;
            float nrm = dinv_t[s] * __int_as_float(ent.y) * dv;
            sj[r] = s;
            nj[r] = nrm;
            bp[j].y = __float_as_int(nrm);  // layer 2 reuses nrm
        }
    }

    const float2* xw = reinterpret_cast<const float2*>(g_xW1);

    float2 me = xw[node * 32 + lane];       // self-loop, norm = dv*dv
    float accx = me.x * (dv * dv);
    float accy = me.y * (dv * dv);

#pragma unroll
    for (int r = 0; r < 3; r++) {
        int cnt = min(max(c - 32 * r, 0), 32);
#pragma unroll 8
        for (int k = 0; k < cnt; k++) {
            int   s   = __shfl_sync(0xffffffffu, sj[r], k);
            float nrm = __shfl_sync(0xffffffffu, nj[r], k);
            float2 v = xw[s * 32 + lane];   // independent 256B row loads
            accx = fmaf(v.x, nrm, accx);
            accy = fmaf(v.y, nrm, accy);
        }
    }

    float2 bb = reinterpret_cast<const float2*>(b1)[lane];
    float h0 = fmaxf(accx + bb.x, 0.0f);
    float h1 = fmaxf(accy + bb.y, 0.0f);

    // z[lane] = sum_k h[k] * W2[k][lane]   (64 shfl + 64 fma, weights in regs)
    float z = 0.f;
#pragma unroll
    for (int j = 0; j < 32; j++) {
        float a = __shfl_sync(0xffffffffu, h0, j);
        float b = __shfl_sync(0xffffffffu, h1, j);
        z = fmaf(a, wreg[2 * j],     z);
        z = fmaf(b, wreg[2 * j + 1], z);
    }
    g_hW2[(size_t)base * ZD + lane] = z;
}

// ============================================================
// Fused layer 2 (ALL t): gather(hW2[t]) + b2 + tanh -> out[t]
// Warp per (t, node); lane = output dim. Bin entries hold nrm already.
// ============================================================
__global__ void __launch_bounds__(256) k_layer2(const float* __restrict__ b2,
                                                float* __restrict__ out) {
    int t    = blockIdx.y;
    int node = blockIdx.x * (blockDim.x >> 5) + (threadIdx.x >> 5);
    int lane = threadIdx.x & 31;
    if (node >= N_NODES) return;

    int base = t * N_NODES + node;
    float dv = g_dinv[base];
    int   c  = min(g_count[base], CAP);
    const int2* bp = g_bins + (size_t)base * CAP;
    const float* hw = g_hW2 + (size_t)t * N_NODES * ZD;

    int   sj[3];
    float nj[3];
#pragma unroll
    for (int r = 0; r < 3; r++) {
        int j = lane + 32 * r;
        sj[r] = 0; nj[r] = 0.f;
        if (j < c) {
            int2 ent = bp[j];
            sj[r] = ent.x;
            nj[r] = __int_as_float(ent.y);  // nrm
        }
    }

    float acc = hw[node * ZD + lane] * (dv * dv);  // self-loop

#pragma unroll
    for (int r = 0; r < 3; r++) {
        int cnt = min(max(c - 32 * r, 0), 32);
#pragma unroll 8
        for (int k = 0; k < cnt; k++) {
            int   s   = __shfl_sync(0xffffffffu, sj[r], k);
            float nrm = __shfl_sync(0xffffffffu, nj[r], k);
            acc = fmaf(hw[s * ZD + lane], nrm, acc);  // 128B rows
        }
    }
    out[(size_t)base * ZD + lane] = tanhf(acc + b2[lane]);
}

// ============================================================
// Launch
// ============================================================
extern "C" void kernel_launch(void* const* d_in, const int* in_sizes, int n_in,
                              void* d_out, int out_size) {
    const float* x  = (const float*)d_in[0];   // [N, 128]
    const int*   ei = (const int*)d_in[1];     // [T, 2, E]
    const float* ew = (const float*)d_in[2];   // [T, E]
    const float* W1 = (const float*)d_in[3];   // [128, 64]
    const float* b1 = (const float*)d_in[4];   // [64]
    const float* W2 = (const float*)d_in[5];   // [64, 32]
    const float* b2 = (const float*)d_in[6];   // [32]
    float* out = (float*)d_out;                // [T, N, 32]

    const int B = 256;
    const int WPB = B / 32;

    k_xw1<<<(N_NODES + WPB - 1) / WPB, B>>>(x, W1);

    k_init<<<(T_STEPS * N_NODES + B - 1) / B, B>>>();
    k_bin<<<(T_STEPS * E_EDGES + B - 1) / B, B>>>(ei, ew);
    k_dinv<<<(T_STEPS * N_NODES + WPB - 1) / WPB, B>>>();

    dim3 gridL((N_NODES + WPB - 1) / WPB, T_STEPS);
    k_layer1<<<gridL, B>>>(b1, W2);
    k_layer2<<<gridL, B>>>(b2, out);
}

// round 5
// speedup vs baseline: 1.1976x; 1.1976x over previous
#include <cuda_runtime.h>

#define N_NODES 50000
#define T_STEPS 8
#define E_EDGES 800000
#define XD 128
#define HD 64
#define ZD 32
#define CAP 64     // max in-degree; Poisson(16) tail beyond 64 ~ 1e-21 per node
#define WPITCH 68  // padded row pitch (words) for transposed W2 in smem

// ---- scratch (no allocations allowed) ----
__device__ float g_xW1[N_NODES * HD];                       // x @ W1 (12.8 MB)
__device__ float g_hW2[N_NODES * ZD];                       // per-step (6.4 MB)
__device__ float g_deg [T_STEPS * N_NODES];                 // weighted degree
__device__ float g_dinv[T_STEPS * N_NODES];                 // rsqrt(deg)
__device__ int   g_count[T_STEPS * N_NODES];                // in-degree counters
__device__ int2  g_bins[(size_t)T_STEPS * N_NODES * CAP];   // (src, bits(w|nrm)) (205 MB)

// ============================================================
// Setup: g_xW1 = x @ W1   (warp per node, W1 in shared)
// ============================================================
__global__ void k_xw1(const float* __restrict__ x, const float* __restrict__ W1) {
    __shared__ float sW[XD * HD];  // 32 KB
    for (int i = threadIdx.x; i < XD * HD; i += blockDim.x) sW[i] = W1[i];
    __syncthreads();

    int node = blockIdx.x * (blockDim.x >> 5) + (threadIdx.x >> 5);
    int lane = threadIdx.x & 31;
    if (node >= N_NODES) return;

    const float* xr = x + node * XD;
    float xv[4];
    xv[0] = xr[lane];
    xv[1] = xr[lane + 32];
    xv[2] = xr[lane + 64];
    xv[3] = xr[lane + 96];

    float a0 = 0.f, a1 = 0.f;
#pragma unroll
    for (int q = 0; q < 4; q++) {
#pragma unroll
        for (int k = 0; k < 32; k++) {
            float xk = __shfl_sync(0xffffffffu, xv[q], k);
            int kk = q * 32 + k;
            a0 = fmaf(xk, sW[kk * HD + lane], a0);
            a1 = fmaf(xk, sW[kk * HD + lane + 32], a1);
        }
    }
    g_xW1[node * HD + lane]      = a0;
    g_xW1[node * HD + lane + 32] = a1;
}

// ============================================================
// Batched binning for ALL T steps (R3 scheme: deg via atomics)
// ============================================================
__global__ void k_init() {
    int i = blockIdx.x * blockDim.x + threadIdx.x;
    if (i < T_STEPS * N_NODES) { g_deg[i] = 1.0f; g_count[i] = 0; }
}

__global__ void k_bin(const int* __restrict__ ei, const float* __restrict__ ew) {
    int idx = blockIdx.x * blockDim.x + threadIdx.x;
    if (idx >= T_STEPS * E_EDGES) return;
    int t = idx / E_EDGES;
    int e = idx - t * E_EDGES;
    const int* src = ei + (size_t)t * 2 * E_EDGES;
    const int* dst = src + E_EDGES;
    int s = src[e];
    int d = dst[e];
    float w = ew[(size_t)t * E_EDGES + e];
    int base = t * N_NODES + d;
    atomicAdd(&g_deg[base], w);
    int p = atomicAdd(&g_count[base], 1);
    if (p < CAP) g_bins[(size_t)base * CAP + p] = make_int2(s, __float_as_int(w));
}

__global__ void k_dinv() {
    int i = blockIdx.x * blockDim.x + threadIdx.x;
    if (i < T_STEPS * N_NODES) g_dinv[i] = rsqrtf(g_deg[i]);
}

// ============================================================
// Fused layer 1: gather(xW1) + b1 + relu + (h @ W2) -> g_hW2
// Warp per node; lane owns dims {2*lane, 2*lane+1}.
// GEMM tail: h -> per-warp smem, z via float4 LDS from transposed W2.
// Prefetch converts bin w -> nrm (reused by layer 2).
// ============================================================
__global__ void __launch_bounds__(256) k_layer1(const float* __restrict__ b1,
                                                const float* __restrict__ W2,
                                                int t) {
    __shared__ float sWT[ZD * WPITCH];   // W2 transposed [32][64], pitch 68 (8.5 KB)
    __shared__ float sH[8][HD];          // per-warp h (8 warps * 64 floats = 2 KB)
    for (int i = threadIdx.x; i < ZD * HD; i += blockDim.x) {
        int col = i >> 6;                // 0..31
        int k   = i & 63;                // 0..63
        sWT[col * WPITCH + k] = W2[k * ZD + col];
    }
    __syncthreads();

    int wid  = threadIdx.x >> 5;
    int node = blockIdx.x * (blockDim.x >> 5) + wid;
    int lane = threadIdx.x & 31;
    if (node >= N_NODES) return;

    int base = t * N_NODES + node;
    float dv = g_dinv[base];
    int   c  = min(g_count[base], CAP);
    const float* dinv_t = g_dinv + t * N_NODES;
    int2* bp = g_bins + (size_t)base * CAP;

    // coalesced prefetch: lane handles entries lane, lane+32
    int   sj[2];
    float nj[2];
#pragma unroll
    for (int r = 0; r < 2; r++) {
        int j = lane + 32 * r;
        sj[r] = 0; nj[r] = 0.f;
        if (j < c) {
            int2 ent = bp[j];
            int s = ent.x;
            float nrm = dinv_t[s] * __int_as_float(ent.y) * dv;
            sj[r] = s;
            nj[r] = nrm;
            bp[j].y = __float_as_int(nrm);  // layer 2 reuses nrm
        }
    }

    const float2* xw = reinterpret_cast<const float2*>(g_xW1);

    float2 me = xw[node * 32 + lane];       // self-loop, norm = dv*dv
    float accx = me.x * (dv * dv);
    float accy = me.y * (dv * dv);

#pragma unroll
    for (int r = 0; r < 2; r++) {
        int cnt = min(max(c - 32 * r, 0), 32);
#pragma unroll 8
        for (int k = 0; k < cnt; k++) {
            int   s   = __shfl_sync(0xffffffffu, sj[r], k);
            float nrm = __shfl_sync(0xffffffffu, nj[r], k);
            float2 v = xw[s * 32 + lane];   // independent 256B row loads
            accx = fmaf(v.x, nrm, accx);
            accy = fmaf(v.y, nrm, accy);
        }
    }

    float2 bb = reinterpret_cast<const float2*>(b1)[lane];
    sH[wid][2 * lane]     = fmaxf(accx + bb.x, 0.0f);
    sH[wid][2 * lane + 1] = fmaxf(accy + bb.y, 0.0f);
    __syncwarp();

    // z[lane] = sum_k h[k] * W2[k][lane] ; float4 x float4, 16 iters
    const float4* h4 = reinterpret_cast<const float4*>(sH[wid]);
    const float*  wc = sWT + lane * WPITCH;
    float z = 0.f;
#pragma unroll
    for (int q = 0; q < 16; q++) {
        float4 hv = h4[q];                                   // broadcast LDS.128
        float4 wv = *reinterpret_cast<const float4*>(wc + 4 * q);  // conflict-free
        z = fmaf(hv.x, wv.x, z);
        z = fmaf(hv.y, wv.y, z);
        z = fmaf(hv.z, wv.z, z);
        z = fmaf(hv.w, wv.w, z);
    }
    g_hW2[node * ZD + lane] = z;
}

// ============================================================
// Fused layer 2: gather(hW2) + b2 + tanh -> out_t
// Warp per node; lane = output dim. Bin entries hold nrm already.
// ============================================================
__global__ void __launch_bounds__(256) k_layer2(const float* __restrict__ b2,
                                                float* __restrict__ out_t,
                                                int t) {
    int node = blockIdx.x * (blockDim.x >> 5) + (threadIdx.x >> 5);
    int lane = threadIdx.x & 31;
    if (node >= N_NODES) return;

    int base = t * N_NODES + node;
    float dv = g_dinv[base];
    int   c  = min(g_count[base], CAP);
    const int2* bp = g_bins + (size_t)base * CAP;

    int   sj[2];
    float nj[2];
#pragma unroll
    for (int r = 0; r < 2; r++) {
        int j = lane + 32 * r;
        sj[r] = 0; nj[r] = 0.f;
        if (j < c) {
            int2 ent = bp[j];
            sj[r] = ent.x;
            nj[r] = __int_as_float(ent.y);  // nrm
        }
    }

    float acc = g_hW2[node * ZD + lane] * (dv * dv);  // self-loop

#pragma unroll
    for (int r = 0; r < 2; r++) {
        int cnt = min(max(c - 32 * r, 0), 32);
#pragma unroll 8
        for (int k = 0; k < cnt; k++) {
            int   s   = __shfl_sync(0xffffffffu, sj[r], k);
            float nrm = __shfl_sync(0xffffffffu, nj[r], k);
            acc = fmaf(g_hW2[s * ZD + lane], nrm, acc);  // 128B rows
        }
    }
    out_t[node * ZD + lane] = tanhf(acc + b2[lane]);
}

// ============================================================
// Launch
// ============================================================
extern "C" void kernel_launch(void* const* d_in, const int* in_sizes, int n_in,
                              void* d_out, int out_size) {
    const float* x  = (const float*)d_in[0];   // [N, 128]
    const int*   ei = (const int*)d_in[1];     // [T, 2, E]
    const float* ew = (const float*)d_in[2];   // [T, E]
    const float* W1 = (const float*)d_in[3];   // [128, 64]
    const float* b1 = (const float*)d_in[4];   // [64]
    const float* W2 = (const float*)d_in[5];   // [64, 32]
    const float* b2 = (const float*)d_in[6];   // [32]
    float* out = (float*)d_out;                // [T, N, 32]

    const int B = 256;
    const int WPB = B / 32;

    k_xw1<<<(N_NODES + WPB - 1) / WPB, B>>>(x, W1);

    k_init<<<(T_STEPS * N_NODES + B - 1) / B, B>>>();
    k_bin<<<(T_STEPS * E_EDGES + B - 1) / B, B>>>(ei, ew);
    k_dinv<<<(T_STEPS * N_NODES + B - 1) / B, B>>>();

    for (int t = 0; t < T_STEPS; t++) {
        float* out_t = out + (size_t)t * N_NODES * ZD;
        k_layer1<<<(N_NODES + WPB - 1) / WPB, B>>>(b1, W2, t);
        k_layer2<<<(N_NODES + WPB - 1) / WPB, B>>>(b2, out_t, t);
    }
}

// round 6
// speedup vs baseline: 1.7968x; 1.5004x over previous
#include <cuda_runtime.h>

#define N_NODES 50000
#define T_STEPS 8
#define E_EDGES 800000
#define XD 128
#define HD 64
#define ZD 32
#define CAP 96   // max in-degree capacity; Poisson(16) tail beyond 96 ~ e^-80

// ---- scratch (no allocations allowed) ----
__device__ float g_xW1[N_NODES * HD];                       // x @ W1 (12.8 MB)
__device__ float g_hW2[2][N_NODES * ZD];                    // double-buffered (12.8 MB)
__device__ unsigned long long g_pack[T_STEPS * N_NODES];    // (count<<52) | fixed32(sum w)
__device__ float g_dinv[T_STEPS * N_NODES];                 // rsqrt(deg)
__device__ int   g_count[T_STEPS * N_NODES];                // unpacked in-degree
__device__ int2  g_bins[(size_t)T_STEPS * N_NODES * CAP];   // (src, bits(w|nrm)) (307 MB)

// ============================================================
// Setup: g_xW1 = x @ W1   (warp per node, W1 in shared)
// ============================================================
__global__ void k_xw1(const float* __restrict__ x, const float* __restrict__ W1) {
    __shared__ float sW[XD * HD];  // 32 KB
    for (int i = threadIdx.x; i < XD * HD; i += blockDim.x) sW[i] = W1[i];
    __syncthreads();

    int node = blockIdx.x * (blockDim.x >> 5) + (threadIdx.x >> 5);
    int lane = threadIdx.x & 31;
    if (node >= N_NODES) return;

    const float* xr = x + node * XD;
    float xv[4];
    xv[0] = xr[lane];
    xv[1] = xr[lane + 32];
    xv[2] = xr[lane + 64];
    xv[3] = xr[lane + 96];

    float a0 = 0.f, a1 = 0.f;
#pragma unroll
    for (int q = 0; q < 4; q++) {
#pragma unroll
        for (int k = 0; k < 32; k++) {
            float xk = __shfl_sync(0xffffffffu, xv[q], k);
            int kk = q * 32 + k;
            a0 = fmaf(xk, sW[kk * HD + lane], a0);
            a1 = fmaf(xk, sW[kk * HD + lane + 32], a1);
        }
    }
    g_xW1[node * HD + lane]      = a0;
    g_xW1[node * HD + lane + 32] = a1;
}

// ============================================================
// Batched binning for ALL T steps — ONE packed atomic per edge
// ============================================================
__global__ void k_init() {
    int i = blockIdx.x * blockDim.x + threadIdx.x;
    if (i < T_STEPS * N_NODES) g_pack[i] = 0ull;
}

__global__ void k_bin(const int* __restrict__ ei, const float* __restrict__ ew) {
    int idx = blockIdx.x * blockDim.x + threadIdx.x;
    if (idx >= T_STEPS * E_EDGES) return;
    int t = idx / E_EDGES;
    int e = idx - t * E_EDGES;
    const int* src = ei + (size_t)t * 2 * E_EDGES;
    const int* dst = src + E_EDGES;
    int s = src[e];
    int d = dst[e];
    float w = ew[(size_t)t * E_EDGES + e];
    int base = t * N_NODES + d;

    // one atomic: count in bits [52..], weighted degree in 32.32 fixed point below
    unsigned long long add =
        (1ull << 52) | (unsigned long long)(w * 4294967296.0f);
    unsigned long long old = atomicAdd(&g_pack[base], add);
    int p = (int)(old >> 52);
    if (p < CAP) g_bins[(size_t)base * CAP + p] = make_int2(s, __float_as_int(w));
}

__global__ void k_dinv() {
    int i = blockIdx.x * blockDim.x + threadIdx.x;
    if (i >= T_STEPS * N_NODES) return;
    unsigned long long v = g_pack[i];
    g_count[i] = (int)(v >> 52);
    float deg = 1.0f + (float)(v & ((1ull << 52) - 1ull)) * (1.0f / 4294967296.0f);
    g_dinv[i] = rsqrtf(deg);
}

// ============================================================
// Layer bodies (exact R3 hot loops)
// ============================================================
__device__ __forceinline__ void layer1_work(const float* __restrict__ b1,
                                            const float* sW, int t,
                                            float* __restrict__ hw,
                                            int node, int lane) {
    int base = t * N_NODES + node;
    float dv = g_dinv[base];
    int   c  = min(g_count[base], CAP);
    const float* dinv_t = g_dinv + t * N_NODES;
    int2* bp = g_bins + (size_t)base * CAP;

    // coalesced prefetch: lane handles entries lane, lane+32, lane+64
    int   sj[3];
    float nj[3];
#pragma unroll
    for (int r = 0; r < 3; r++) {
        int j = lane + 32 * r;
        sj[r] = 0; nj[r] = 0.f;
        if (j < c) {
            int2 ent = bp[j];
            int s = ent.x;
            float nrm = dinv_t[s] * __int_as_float(ent.y) * dv;
            sj[r] = s;
            nj[r] = nrm;
            bp[j].y = __float_as_int(nrm);  // layer 2 reuses nrm
        }
    }

    const float2* xw = reinterpret_cast<const float2*>(g_xW1);

    float2 me = xw[node * 32 + lane];       // self-loop, norm = dv*dv
    float accx = me.x * (dv * dv);
    float accy = me.y * (dv * dv);

#pragma unroll
    for (int r = 0; r < 3; r++) {
        int cnt = min(max(c - 32 * r, 0), 32);
#pragma unroll 8
        for (int k = 0; k < cnt; k++) {
            int   s   = __shfl_sync(0xffffffffu, sj[r], k);
            float nrm = __shfl_sync(0xffffffffu, nj[r], k);
            float2 v = xw[s * 32 + lane];   // independent 256B row loads
            accx = fmaf(v.x, nrm, accx);
            accy = fmaf(v.y, nrm, accy);
        }
    }

    float2 bb = reinterpret_cast<const float2*>(b1)[lane];
    float h0 = fmaxf(accx + bb.x, 0.0f);
    float h1 = fmaxf(accy + bb.y, 0.0f);

    float z = 0.f;
#pragma unroll
    for (int k = 0; k < 32; k++) {
        float hk0 = __shfl_sync(0xffffffffu, h0, k);
        float hk1 = __shfl_sync(0xffffffffu, h1, k);
        z = fmaf(hk0, sW[(2 * k) * ZD + lane], z);
        z = fmaf(hk1, sW[(2 * k + 1) * ZD + lane], z);
    }
    hw[node * ZD + lane] = z;
}

__device__ __forceinline__ void layer2_work(const float* __restrict__ b2,
                                            const float* __restrict__ hw,
                                            float* __restrict__ out_t, int t,
                                            int node, int lane) {
    int base = t * N_NODES + node;
    float dv = g_dinv[base];
    int   c  = min(g_count[base], CAP);
    const int2* bp = g_bins + (size_t)base * CAP;

    int   sj[3];
    float nj[3];
#pragma unroll
    for (int r = 0; r < 3; r++) {
        int j = lane + 32 * r;
        sj[r] = 0; nj[r] = 0.f;
        if (j < c) {
            int2 ent = bp[j];
            sj[r] = ent.x;
            nj[r] = __int_as_float(ent.y);  // nrm (written by layer 1)
        }
    }

    float acc = hw[node * ZD + lane] * (dv * dv);  // self-loop

#pragma unroll
    for (int r = 0; r < 3; r++) {
        int cnt = min(max(c - 32 * r, 0), 32);
#pragma unroll 8
        for (int k = 0; k < cnt; k++) {
            int   s   = __shfl_sync(0xffffffffu, sj[r], k);
            float nrm = __shfl_sync(0xffffffffu, nj[r], k);
            acc = fmaf(hw[s * ZD + lane], nrm, acc);  // 128B rows
        }
    }
    out_t[node * ZD + lane] = tanhf(acc + b2[lane]);
}

// ============================================================
// Launch wrappers
// ============================================================
__global__ void k_layer1(const float* __restrict__ b1, const float* __restrict__ W2,
                         int t, float* __restrict__ hw) {
    __shared__ float sW[HD * ZD];  // 8 KB
    for (int i = threadIdx.x; i < HD * ZD; i += blockDim.x) sW[i] = W2[i];
    __syncthreads();
    int node = blockIdx.x * (blockDim.x >> 5) + (threadIdx.x >> 5);
    int lane = threadIdx.x & 31;
    if (node >= N_NODES) return;
    layer1_work(b1, sW, t, hw, node, lane);
}

// blockIdx.y == 1: layer1 for step t (writes hw_w);  y == 0: layer2 for step t-1
__global__ void k_combined(const float* __restrict__ b1, const float* __restrict__ W2,
                           const float* __restrict__ b2,
                           float* __restrict__ out_prev, int t,
                           const float* __restrict__ hw_r, float* __restrict__ hw_w) {
    __shared__ float sW[HD * ZD];
    int node = blockIdx.x * (blockDim.x >> 5) + (threadIdx.x >> 5);
    int lane = threadIdx.x & 31;
    if (blockIdx.y == 1) {
        for (int i = threadIdx.x; i < HD * ZD; i += blockDim.x) sW[i] = W2[i];
        __syncthreads();
        if (node >= N_NODES) return;
        layer1_work(b1, sW, t, hw_w, node, lane);
    } else {
        if (node >= N_NODES) return;
        layer2_work(b2, hw_r, out_prev, t - 1, node, lane);
    }
}

__global__ void k_layer2(const float* __restrict__ b2, float* __restrict__ out_t,
                         int t, const float* __restrict__ hw) {
    int node = blockIdx.x * (blockDim.x >> 5) + (threadIdx.x >> 5);
    int lane = threadIdx.x & 31;
    if (node >= N_NODES) return;
    layer2_work(b2, hw, out_t, t, node, lane);
}

// ============================================================
// Launch
// ============================================================
extern "C" void kernel_launch(void* const* d_in, const int* in_sizes, int n_in,
                              void* d_out, int out_size) {
    const float* x  = (const float*)d_in[0];   // [N, 128]
    const int*   ei = (const int*)d_in[1];     // [T, 2, E]
    const float* ew = (const float*)d_in[2];   // [T, E]
    const float* W1 = (const float*)d_in[3];   // [128, 64]
    const float* b1 = (const float*)d_in[4];   // [64]
    const float* W2 = (const float*)d_in[5];   // [64, 32]
    const float* b2 = (const float*)d_in[6];   // [32]
    float* out = (float*)d_out;                // [T, N, 32]

    const int B = 256;
    const int WPB = B / 32;
    const int NB = (N_NODES + WPB - 1) / WPB;

    k_xw1<<<NB, B>>>(x, W1);

    k_init<<<(T_STEPS * N_NODES + B - 1) / B, B>>>();
    k_bin<<<(T_STEPS * E_EDGES + B - 1) / B, B>>>(ei, ew);
    k_dinv<<<(T_STEPS * N_NODES + B - 1) / B, B>>>();

    // resolve hW2 buffer addresses once (device symbol -> pointer math on host side
    // is not allowed; pass buffer index via pointer arithmetic inside kernels instead)
    // g_hW2[t & 1] selected by passing the raw pointers:
    float* hw0; float* hw1;
    cudaGetSymbolAddress((void**)&hw0, g_hW2);
    hw1 = hw0 + (size_t)N_NODES * ZD;

    // t = 0: layer1 only
    k_layer1<<<NB, B>>>(b1, W2, 0, hw0);
    // t = 1..7: layer2(t-1) || layer1(t), double-buffered
    for (int t = 1; t < T_STEPS; t++) {
        float* out_prev = out + (size_t)(t - 1) * N_NODES * ZD;
        float* hw_r = (t & 1) ? hw0 : hw1;   // written by layer1(t-1)
        float* hw_w = (t & 1) ? hw1 : hw0;
        dim3 grid(NB, 2);
        k_combined<<<grid, B>>>(b1, W2, b2, out_prev, t, hw_r, hw_w);
    }
    // final layer2 for t = 7
    k_layer2<<<NB, B>>>(b2, out + (size_t)7 * N_NODES * ZD, 7,
                        (7 & 1) ? hw1 : hw0);
}

// round 7
// speedup vs baseline: 1.8119x; 1.0084x over previous
#include <cuda_runtime.h>

#define N_NODES 50000
#define T_STEPS 8
#define E_EDGES 800000
#define XD 128
#define HD 64
#define ZD 32
#define CAP 96       // Poisson(16) tail beyond 96 ~ e^-80

#define NB_L   6250  // layer role blocks: 50000 nodes / 8 warps per block
#define NB_BIN 3125  // bin role blocks: 800000 edges / 256
#define NB_DNV 196   // dinv role blocks: 50000 / 256

// ---- scratch (no allocations allowed) ----
__device__ float g_xW1[N_NODES * HD];                       // x @ W1 (12.8 MB)
__device__ float g_hW2[2][N_NODES * ZD];                    // double-buffered
__device__ unsigned long long g_pack[T_STEPS * N_NODES];    // (count<<52)|fixed32(sum w)
__device__ float g_dinv[T_STEPS * N_NODES];
__device__ int   g_count[T_STEPS * N_NODES];
__device__ int2  g_bins[(size_t)T_STEPS * N_NODES * CAP];   // (src, bits(w|nrm)) (307 MB)

// ============================================================
// Setup: g_xW1 = x @ W1   (warp per node, W1 in shared)
// ============================================================
__global__ void k_xw1(const float* __restrict__ x, const float* __restrict__ W1) {
    __shared__ float sW[XD * HD];
    for (int i = threadIdx.x; i < XD * HD; i += blockDim.x) sW[i] = W1[i];
    __syncthreads();

    int node = blockIdx.x * (blockDim.x >> 5) + (threadIdx.x >> 5);
    int lane = threadIdx.x & 31;
    if (node >= N_NODES) return;

    const float* xr = x + node * XD;
    float xv[4];
    xv[0] = xr[lane];
    xv[1] = xr[lane + 32];
    xv[2] = xr[lane + 64];
    xv[3] = xr[lane + 96];

    float a0 = 0.f, a1 = 0.f;
#pragma unroll
    for (int q = 0; q < 4; q++) {
#pragma unroll
        for (int k = 0; k < 32; k++) {
            float xk = __shfl_sync(0xffffffffu, xv[q], k);
            int kk = q * 32 + k;
            a0 = fmaf(xk, sW[kk * HD + lane], a0);
            a1 = fmaf(xk, sW[kk * HD + lane + 32], a1);
        }
    }
    g_xW1[node * HD + lane]      = a0;
    g_xW1[node * HD + lane + 32] = a1;
}

// ============================================================
// Work bodies
// ============================================================
__global__ void k_init() {
    int i = blockIdx.x * blockDim.x + threadIdx.x;
    if (i < T_STEPS * N_NODES) g_pack[i] = 0ull;
}

__device__ __forceinline__ void bin_work(int t, int e, const int* __restrict__ ei,
                                         const float* __restrict__ ew) {
    const int* src = ei + (size_t)t * 2 * E_EDGES;
    const int* dst = src + E_EDGES;
    int s = src[e];
    int d = dst[e];
    float w = ew[(size_t)t * E_EDGES + e];
    int base = t * N_NODES + d;
    unsigned long long add =
        (1ull << 52) | (unsigned long long)(w * 4294967296.0f);
    unsigned long long old = atomicAdd(&g_pack[base], add);
    int p = (int)(old >> 52);
    if (p < CAP) g_bins[(size_t)base * CAP + p] = make_int2(s, __float_as_int(w));
}

__device__ __forceinline__ void dinv_work(int i) {
    unsigned long long v = g_pack[i];
    g_count[i] = (int)(v >> 52);
    float deg = 1.0f + (float)(v & ((1ull << 52) - 1ull)) * (1.0f / 4294967296.0f);
    g_dinv[i] = rsqrtf(deg);
}

__device__ __forceinline__ void layer1_work(const float* __restrict__ b1,
                                            const float* sW, int t,
                                            float* __restrict__ hw,
                                            int node, int lane) {
    int base = t * N_NODES + node;
    float dv = g_dinv[base];
    int   c  = min(g_count[base], CAP);
    const float* dinv_t = g_dinv + t * N_NODES;
    int2* bp = g_bins + (size_t)base * CAP;

    int   sj[3];
    float nj[3];
#pragma unroll
    for (int r = 0; r < 3; r++) {
        int j = lane + 32 * r;
        sj[r] = 0; nj[r] = 0.f;
        if (j < c) {
            int2 ent = bp[j];
            int s = ent.x;
            float nrm = dinv_t[s] * __int_as_float(ent.y) * dv;
            sj[r] = s;
            nj[r] = nrm;
            bp[j].y = __float_as_int(nrm);  // layer 2 reuses nrm
        }
    }

    const float2* xw = reinterpret_cast<const float2*>(g_xW1);

    float2 me = xw[node * 32 + lane];
    float accx = me.x * (dv * dv);
    float accy = me.y * (dv * dv);

#pragma unroll
    for (int r = 0; r < 3; r++) {
        int cnt = min(max(c - 32 * r, 0), 32);
#pragma unroll 8
        for (int k = 0; k < cnt; k++) {
            int   s   = __shfl_sync(0xffffffffu, sj[r], k);
            float nrm = __shfl_sync(0xffffffffu, nj[r], k);
            float2 v = xw[s * 32 + lane];
            accx = fmaf(v.x, nrm, accx);
            accy = fmaf(v.y, nrm, accy);
        }
    }

    float2 bb = reinterpret_cast<const float2*>(b1)[lane];
    float h0 = fmaxf(accx + bb.x, 0.0f);
    float h1 = fmaxf(accy + bb.y, 0.0f);

    float z = 0.f;
#pragma unroll
    for (int k = 0; k < 32; k++) {
        float hk0 = __shfl_sync(0xffffffffu, h0, k);
        float hk1 = __shfl_sync(0xffffffffu, h1, k);
        z = fmaf(hk0, sW[(2 * k) * ZD + lane], z);
        z = fmaf(hk1, sW[(2 * k + 1) * ZD + lane], z);
    }
    hw[node * ZD + lane] = z;
}

__device__ __forceinline__ void layer2_work(const float* __restrict__ b2,
                                            const float* __restrict__ hw,
                                            float* __restrict__ out_t, int t,
                                            int node, int lane) {
    int base = t * N_NODES + node;
    float dv = g_dinv[base];
    int   c  = min(g_count[base], CAP);
    const int2* bp = g_bins + (size_t)base * CAP;

    int   sj[3];
    float nj[3];
#pragma unroll
    for (int r = 0; r < 3; r++) {
        int j = lane + 32 * r;
        sj[r] = 0; nj[r] = 0.f;
        if (j < c) {
            int2 ent = bp[j];
            sj[r] = ent.x;
            nj[r] = __int_as_float(ent.y);  // nrm
        }
    }

    float acc = hw[node * ZD + lane] * (dv * dv);

#pragma unroll
    for (int r = 0; r < 3; r++) {
        int cnt = min(max(c - 32 * r, 0), 32);
#pragma unroll 8
        for (int k = 0; k < cnt; k++) {
            int   s   = __shfl_sync(0xffffffffu, sj[r], k);
            float nrm = __shfl_sync(0xffffffffu, nj[r], k);
            acc = fmaf(hw[s * ZD + lane], nrm, acc);
        }
    }
    out_t[node * ZD + lane] = tanhf(acc + b2[lane]);
}

// ============================================================
// Pipelined step kernel: roles by blockIdx.x range
//   [0, NB_L)              layer1(t)            -> hw_w
//   [NB_L, 2*NB_L)         layer2(t-1)          (if t >= 1)
//   [2*NB_L, +NB_BIN)      bin(t+2)             (if t+2 < T)
//   [2*NB_L+NB_BIN, +NB_DNV) dinv(t+1)          (if t+1 < T)
// ============================================================
__global__ void k_step(const float* __restrict__ b1, const float* __restrict__ W2,
                       const float* __restrict__ b2,
                       float* __restrict__ out_prev, int t,
                       const float* __restrict__ hw_r, float* __restrict__ hw_w,
                       const int* __restrict__ ei, const float* __restrict__ ew) {
    int bx = blockIdx.x;
    int lane = threadIdx.x & 31;

    if (bx < NB_L) {
        __shared__ float sW[HD * ZD];
        for (int i = threadIdx.x; i < HD * ZD; i += blockDim.x) sW[i] = W2[i];
        __syncthreads();
        int node = bx * 8 + (threadIdx.x >> 5);
        if (node >= N_NODES) return;
        layer1_work(b1, sW, t, hw_w, node, lane);
    } else if (bx < 2 * NB_L) {
        if (t == 0) return;
        int node = (bx - NB_L) * 8 + (threadIdx.x >> 5);
        if (node >= N_NODES) return;
        layer2_work(b2, hw_r, out_prev, t - 1, node, lane);
    } else if (bx < 2 * NB_L + NB_BIN) {
        int tb = t + 2;
        if (tb >= T_STEPS) return;
        int e = (bx - 2 * NB_L) * 256 + threadIdx.x;
        if (e < E_EDGES) bin_work(tb, e, ei, ew);
    } else {
        int td = t + 1;
        if (td >= T_STEPS) return;
        int i = (bx - 2 * NB_L - NB_BIN) * 256 + threadIdx.x;
        if (i < N_NODES) dinv_work(td * N_NODES + i);
    }
}

// prologue helpers
__global__ void k_bin01(const int* __restrict__ ei, const float* __restrict__ ew) {
    int idx = blockIdx.x * blockDim.x + threadIdx.x;   // 2*E threads
    if (idx >= 2 * E_EDGES) return;
    int t = idx < E_EDGES ? 0 : 1;
    int e = idx - t * E_EDGES;
    bin_work(t, e, ei, ew);
}

__global__ void k_dinv0() {
    int i = blockIdx.x * blockDim.x + threadIdx.x;
    if (i < N_NODES) dinv_work(i);
}

__global__ void k_layer2_last(const float* __restrict__ b2, float* __restrict__ out_t,
                              const float* __restrict__ hw) {
    int node = blockIdx.x * (blockDim.x >> 5) + (threadIdx.x >> 5);
    int lane = threadIdx.x & 31;
    if (node >= N_NODES) return;
    layer2_work(b2, hw, out_t, T_STEPS - 1, node, lane);
}

// ============================================================
// Launch
// ============================================================
extern "C" void kernel_launch(void* const* d_in, const int* in_sizes, int n_in,
                              void* d_out, int out_size) {
    const float* x  = (const float*)d_in[0];   // [N, 128]
    const int*   ei = (const int*)d_in[1];     // [T, 2, E]
    const float* ew = (const float*)d_in[2];   // [T, E]
    const float* W1 = (const float*)d_in[3];   // [128, 64]
    const float* b1 = (const float*)d_in[4];   // [64]
    const float* W2 = (const float*)d_in[5];   // [64, 32]
    const float* b2 = (const float*)d_in[6];   // [32]
    float* out = (float*)d_out;                // [T, N, 32]

    const int B = 256;

    float* hw0; float* hw1;
    cudaGetSymbolAddress((void**)&hw0, g_hW2);
    hw1 = hw0 + (size_t)N_NODES * ZD;

    // prologue
    k_init<<<(T_STEPS * N_NODES + B - 1) / B, B>>>();
    k_xw1<<<NB_L, B>>>(x, W1);
    k_bin01<<<(2 * E_EDGES + B - 1) / B, B>>>(ei, ew);
    k_dinv0<<<(N_NODES + B - 1) / B, B>>>();

    // pipelined steps
    const int GRID = 2 * NB_L + NB_BIN + NB_DNV;
    for (int t = 0; t < T_STEPS; t++) {
        float* out_prev = out + (size_t)(t - 1) * N_NODES * ZD;  // unused at t=0
        float* hw_r = (t & 1) ? hw0 : hw1;
        float* hw_w = (t & 1) ? hw1 : hw0;
        k_step<<<GRID, B>>>(b1, W2, b2, out_prev, t, hw_r, hw_w, ei, ew);
    }

    // epilogue: layer2 for t = 7
    k_layer2_last<<<NB_L, B>>>(b2, out + (size_t)(T_STEPS - 1) * N_NODES * ZD,
                               ((T_STEPS - 1) & 1) ? hw1 : hw0);
}